// round 1
// baseline (speedup 1.0000x reference)
#include <cuda_runtime.h>
#include <cuda_bf16.h>
#include <cstdint>

// ---------------------------------------------------------------------------
// GRU, 6 layers: T=512, B=256, I=128, H=256, G=3H=768
// Output: cur [T,B,H] fp32 followed by finals [L,B,H] fp32.
// ---------------------------------------------------------------------------

#define T_LEN 512
#define B_SZ  256
#define I_SZ  128
#define H_SZ  256
#define G_SZ  768
#define L_NUM 6

#define M_ROWS (T_LEN * B_SZ)          // 131072
#define TBH    (T_LEN * B_SZ * H_SZ)   // 33554432
#define BH     (B_SZ * H_SZ)           // 65536

typedef unsigned long long ull;

// ------------------------------ scratch -----------------------------------
__device__ float g_gx[(size_t)T_LEN * B_SZ * G_SZ];   // 402 MB
__device__ float g_buf[2ULL * TBH];                   // 256 MB layer ping-pong
__device__ float g_h[2ULL * BH];                      // h double buffer
__device__ ull   g_bar_ctr;                           // monotonic grid barrier

// ------------------------------ helpers -----------------------------------
__device__ __forceinline__ ull pack2(float x, float y) {
    ull r; asm("mov.b64 %0, {%1, %2};" : "=l"(r) : "f"(x), "f"(y)); return r;
}
__device__ __forceinline__ float2 unpack2(ull v) {
    float2 r; asm("mov.b64 {%0, %1}, %2;" : "=f"(r.x), "=f"(r.y) : "l"(v)); return r;
}
__device__ __forceinline__ void fma2(ull& d, ull a, ull b) {
    asm("fma.rn.f32x2 %0, %1, %2, %0;" : "+l"(d) : "l"(a), "l"(b));
}
__device__ __forceinline__ float sigmf(float x) {
    return 1.0f / (1.0f + expf(-x));
}

// Monotonic-counter grid barrier: works across graph replays (never reset).
__device__ __forceinline__ void grid_barrier(unsigned nb) {
    __syncthreads();
    if (threadIdx.x == 0) {
        __threadfence();
        ull tok = atomicAdd(&g_bar_ctr, 1ULL) + 1ULL;
        ull target = ((tok + nb - 1ULL) / nb) * (ull)nb;
        for (;;) {
            ull v;
            asm volatile("ld.volatile.global.u64 %0, [%1];" : "=l"(v) : "l"(&g_bar_ctr));
            if (v >= target) break;
        }
        __threadfence();
    }
    __syncthreads();
}

// ------------------------------ copy --------------------------------------
__global__ void copy_kernel(float* __restrict__ dst, const float* __restrict__ src, int n) {
    int i = blockIdx.x * blockDim.x + threadIdx.x;
    if (i < n) dst[i] = src[i];
}

// ---------------------------------------------------------------------------
// Input projection GEMM: C[m][g] = bias[g] + sum_k A[m][k] * W[g][k]
// M = 131072, N = 768, K in {128, 256}. Tile 128x64x32, 256 threads,
// 8x4 per-thread microtile with packed f32x2 FMAs (rows paired).
// ---------------------------------------------------------------------------
__global__ void __launch_bounds__(256)
gemm_gx_kernel(const float* __restrict__ A, const float* __restrict__ W,
               const float* __restrict__ bias, float* __restrict__ C, int K)
{
    __shared__ float As[32][128];
    __shared__ float Bs[32][64];

    const int m0 = blockIdx.x * 128;
    const int n0 = blockIdx.y * 64;
    const int tid = threadIdx.x;
    const int ty = tid >> 4;     // 0..15 -> rows ty*8 .. +7
    const int tx = tid & 15;     // 0..15 -> cols tx*4 .. +3

    ull acc[4][4];
    #pragma unroll
    for (int i = 0; i < 4; ++i)
        #pragma unroll
        for (int j = 0; j < 4; ++j) acc[i][j] = 0ULL;

    const int lrow = tid >> 3;        // 0..31
    const int lcol = (tid & 7) * 4;   // 0..28

    for (int k0 = 0; k0 < K; k0 += 32) {
        // stage A tile (128 x 32), transposed into As[k][m]
        #pragma unroll
        for (int p = 0; p < 4; ++p) {
            int ar = lrow + p * 32;
            float4 v = *(const float4*)(A + (size_t)(m0 + ar) * K + k0 + lcol);
            As[lcol + 0][ar] = v.x; As[lcol + 1][ar] = v.y;
            As[lcol + 2][ar] = v.z; As[lcol + 3][ar] = v.w;
        }
        // stage B tile (64 x 32), transposed into Bs[k][n]
        #pragma unroll
        for (int p = 0; p < 2; ++p) {
            int br = lrow + p * 32;
            float4 v = *(const float4*)(W + (size_t)(n0 + br) * K + k0 + lcol);
            Bs[lcol + 0][br] = v.x; Bs[lcol + 1][br] = v.y;
            Bs[lcol + 2][br] = v.z; Bs[lcol + 3][br] = v.w;
        }
        __syncthreads();

        #pragma unroll 8
        for (int kk = 0; kk < 32; ++kk) {
            const ulonglong2* ap = (const ulonglong2*)(&As[kk][ty * 8]);
            ulonglong2 a01 = ap[0];   // row pairs (0,1),(2,3)
            ulonglong2 a45 = ap[1];   // row pairs (4,5),(6,7)
            ull ar[4] = { a01.x, a01.y, a45.x, a45.y };
            float4 bv = *(const float4*)(&Bs[kk][tx * 4]);
            ull b2[4] = { pack2(bv.x, bv.x), pack2(bv.y, bv.y),
                          pack2(bv.z, bv.z), pack2(bv.w, bv.w) };
            #pragma unroll
            for (int rp = 0; rp < 4; ++rp)
                #pragma unroll
                for (int j = 0; j < 4; ++j)
                    fma2(acc[rp][j], ar[rp], b2[j]);
        }
        __syncthreads();
    }

    float4 bb = *(const float4*)(bias + n0 + tx * 4);
    const float bx[4] = { bb.x, bb.y, bb.z, bb.w };
    #pragma unroll
    for (int rr = 0; rr < 8; ++rr) {
        int rp = rr >> 1, hi = rr & 1;
        float4 o;
        float2 v0 = unpack2(acc[rp][0]);
        float2 v1 = unpack2(acc[rp][1]);
        float2 v2 = unpack2(acc[rp][2]);
        float2 v3 = unpack2(acc[rp][3]);
        o.x = (hi ? v0.y : v0.x) + bx[0];
        o.y = (hi ? v1.y : v1.x) + bx[1];
        o.z = (hi ? v2.y : v2.x) + bx[2];
        o.w = (hi ? v3.y : v3.x) + bx[3];
        int row = m0 + ty * 8 + rr;
        *(float4*)(C + (size_t)row * G_SZ + n0 + tx * 4) = o;
    }
}

// ---------------------------------------------------------------------------
// Persistent recurrent scan for one layer.
// Grid = 128 CTAs (16 b-groups x 8 h-groups), 128 threads/CTA, 1 CTA/SM.
// W_hh slice (96 gate-cols x 256 k) lives transposed in smem for all 512
// steps. h tile (16 x 256) staged to smem each step. Software grid barrier
// between timesteps.
// ---------------------------------------------------------------------------
#define SCAN_SMEM (96 * 256 * 4 + 16 * 260 * 4)   // 114944 bytes

__global__ void __launch_bounds__(128)
gru_scan_kernel(const float* __restrict__ Whh,  // [768][256]
                const float* __restrict__ bhh,  // [768]
                const float* __restrict__ gx,   // [T*B][768]
                float* __restrict__ out,        // [T*B][256]
                float* __restrict__ hbuf)       // [2][B*H]
{
    extern __shared__ float smem[];
    float* Ws = smem;               // [256][96]  (k-major)
    float* hs = smem + 96 * 256;    // [16][260]  (row padded)

    const int tid = threadIdx.x;
    const int bg = blockIdx.x >> 3;   // 0..15
    const int hg = blockIdx.x & 7;    // 0..7
    const int b0 = bg * 16;
    const int h0 = hg * 32;

    // Load + transpose W slice once: Ws[k*96 + j] = Whh[(gt*256 + h0 + col)][k]
    for (int idx = tid; idx < 96 * 256; idx += 128) {
        int j = idx >> 8;          // 0..95
        int k = idx & 255;
        int gt = j >> 5, col = j & 31;
        Ws[k * 96 + j] = Whh[(size_t)(gt * 256 + h0 + col) * 256 + k];
    }

    const int r = tid >> 3;          // 0..15 : b-row within tile
    const int c = tid & 7;           // 0..7  : 4-col group
    const int cb = h0 + c * 4;       // h-column base

    float4 brv = *(const float4*)(bhh + cb);
    float4 bzv = *(const float4*)(bhh + 256 + cb);
    float4 bnv = *(const float4*)(bhh + 512 + cb);

    __syncthreads();

    for (int t = 0; t < T_LEN; ++t) {
        // stage h tile [16 x 256] -> hs (padded rows of 260)
        const float* hsrc = hbuf + (size_t)(t & 1) * BH + (size_t)b0 * 256;
        for (int f = tid; f < 1024; f += 128) {
            int row = f >> 6;
            int kf = (f & 63) << 2;
            *(float4*)(hs + row * 260 + kf) = *(const float4*)(hsrc + row * 256 + kf);
        }
        __syncthreads();

        ull aR0 = 0, aR1 = 0, aZ0 = 0, aZ1 = 0, aN0 = 0, aN1 = 0;
        const float* hr = hs + r * 260;
        const float* wp = Ws + c * 4;

        #pragma unroll 4
        for (int k = 0; k < 256; ++k) {
            float a = hr[k];
            ull a2 = pack2(a, a);
            const float* wk = wp + k * 96;
            ulonglong2 wr = *(const ulonglong2*)(wk);
            ulonglong2 wz = *(const ulonglong2*)(wk + 32);
            ulonglong2 wn = *(const ulonglong2*)(wk + 64);
            fma2(aR0, a2, wr.x); fma2(aR1, a2, wr.y);
            fma2(aZ0, a2, wz.x); fma2(aZ1, a2, wz.y);
            fma2(aN0, a2, wn.x); fma2(aN1, a2, wn.y);
        }

        const int b = b0 + r;
        const float* gxr = gx + ((size_t)t * B_SZ + b) * G_SZ;
        float4 ir  = *(const float4*)(gxr + cb);
        float4 iz  = *(const float4*)(gxr + 256 + cb);
        float4 inn = *(const float4*)(gxr + 512 + cb);
        float4 hp  = *(const float4*)(hr + cb);

        float2 r01 = unpack2(aR0), r23 = unpack2(aR1);
        float2 z01 = unpack2(aZ0), z23 = unpack2(aZ1);
        float2 n01 = unpack2(aN0), n23 = unpack2(aN1);

        float rg0 = sigmf(ir.x + r01.x + brv.x);
        float rg1 = sigmf(ir.y + r01.y + brv.y);
        float rg2 = sigmf(ir.z + r23.x + brv.z);
        float rg3 = sigmf(ir.w + r23.y + brv.w);

        float zg0 = sigmf(iz.x + z01.x + bzv.x);
        float zg1 = sigmf(iz.y + z01.y + bzv.y);
        float zg2 = sigmf(iz.z + z23.x + bzv.z);
        float zg3 = sigmf(iz.w + z23.y + bzv.w);

        float ng0 = tanhf(inn.x + rg0 * (n01.x + bnv.x));
        float ng1 = tanhf(inn.y + rg1 * (n01.y + bnv.y));
        float ng2 = tanhf(inn.z + rg2 * (n23.x + bnv.z));
        float ng3 = tanhf(inn.w + rg3 * (n23.y + bnv.w));

        float4 hv;
        hv.x = (1.0f - zg0) * ng0 + zg0 * hp.x;
        hv.y = (1.0f - zg1) * ng1 + zg1 * hp.y;
        hv.z = (1.0f - zg2) * ng2 + zg2 * hp.z;
        hv.w = (1.0f - zg3) * ng3 + zg3 * hp.w;

        *(float4*)(hbuf + (size_t)((t + 1) & 1) * BH + (size_t)b * 256 + cb) = hv;
        *(float4*)(out + ((size_t)t * B_SZ + b) * 256 + cb) = hv;

        if (t != T_LEN - 1) grid_barrier(128);
    }
}

// ---------------------------------------------------------------------------
extern "C" void kernel_launch(void* const* d_in, const int* in_sizes, int n_in,
                              void* d_out, int out_size)
{
    const float* x     = (const float*)d_in[0];  // [512,256,128]
    const float* h0    = (const float*)d_in[1];  // [6,256,256]
    const float* Wih0  = (const float*)d_in[2];  // [768,128]
    const float* Wih   = (const float*)d_in[3];  // [5,768,256]
    const float* Whh   = (const float*)d_in[4];  // [6,768,256]
    const float* bih   = (const float*)d_in[5];  // [6,768]
    const float* bhh   = (const float*)d_in[6];  // [6,768]
    float* out = (float*)d_out;

    float *gx_p = nullptr, *buf_p = nullptr, *h_p = nullptr;
    cudaGetSymbolAddress((void**)&gx_p,  g_gx);
    cudaGetSymbolAddress((void**)&buf_p, g_buf);
    cudaGetSymbolAddress((void**)&h_p,   g_h);

    cudaFuncSetAttribute(gru_scan_kernel,
                         cudaFuncAttributeMaxDynamicSharedMemorySize, SCAN_SMEM);

    for (int l = 0; l < L_NUM; ++l) {
        const float* in  = (l == 0) ? x   : buf_p + (size_t)((l - 1) & 1) * TBH;
        float*       lo  = (l == L_NUM - 1) ? out : buf_p + (size_t)(l & 1) * TBH;
        const int    K   = (l == 0) ? I_SZ : H_SZ;
        const float* Wi  = (l == 0) ? Wih0 : Wih + (size_t)(l - 1) * G_SZ * H_SZ;
        const float* Wh  = Whh + (size_t)l * G_SZ * H_SZ;
        const float* bi  = bih + (size_t)l * G_SZ;
        const float* bh  = bhh + (size_t)l * G_SZ;

        // h <- h0[l]
        copy_kernel<<<BH / 256, 256>>>(h_p, h0 + (size_t)l * BH, BH);

        // gx = in @ Wi^T + bi   for all timesteps
        dim3 gg(M_ROWS / 128, G_SZ / 64);
        gemm_gx_kernel<<<gg, 256>>>(in, Wi, bi, gx_p, K);

        // recurrent scan (persistent, 128 co-resident CTAs)
        gru_scan_kernel<<<128, 128, SCAN_SMEM>>>(Wh, bh, gx_p, lo, h_p);

        // finals[l] = h after 512 steps (parity 0)
        copy_kernel<<<BH / 256, 256>>>(out + (size_t)TBH + (size_t)l * BH, h_p, BH);
    }
}

// round 2
// speedup vs baseline: 1.1623x; 1.1623x over previous
#include <cuda_runtime.h>
#include <cstdint>

// ---------------------------------------------------------------------------
// GRU, 6 layers: T=512, B=256, I=128, H=256, G=3H=768
// Output: cur [T,B,H] fp32 followed by finals [L,B,H] fp32.
// ---------------------------------------------------------------------------

#define T_LEN 512
#define B_SZ  256
#define I_SZ  128
#define H_SZ  256
#define G_SZ  768
#define L_NUM 6

#define M_ROWS (T_LEN * B_SZ)                  // 131072
#define TBH    ((size_t)T_LEN * B_SZ * H_SZ)   // 33554432
#define BH     (B_SZ * H_SZ)                   // 65536

typedef unsigned long long ull;

// ------------------------------ scratch -----------------------------------
__device__ float g_gx[(size_t)M_ROWS * G_SZ];          // 402 MB
__device__ float g_buf[2ULL * 512 * 256 * 256];        // 256 MB layer ping-pong
__device__ __align__(128) ull g_bar2[16][16];          // per-b-group barrier ctrs

// ------------------------------ helpers -----------------------------------
__device__ __forceinline__ ull pack2(float x, float y) {
    ull r; asm("mov.b64 %0, {%1, %2};" : "=l"(r) : "f"(x), "f"(y)); return r;
}
__device__ __forceinline__ float2 unpack2(ull v) {
    float2 r; asm("mov.b64 {%0, %1}, %2;" : "=f"(r.x), "=f"(r.y) : "l"(v)); return r;
}
__device__ __forceinline__ void fma2(ull& d, ull a, ull b) {
    asm("fma.rn.f32x2 %0, %1, %2, %0;" : "+l"(d) : "l"(a), "l"(b));
}
__device__ __forceinline__ float sigmf(float x) {
    return 1.0f / (1.0f + expf(-x));
}

// 8-CTA barrier per b-group. Monotonic counter: safe across graph replays
// because all 8 members always perform the same number of arrivals.
__device__ __forceinline__ void bg_barrier(int bg) {
    __syncthreads();
    if (threadIdx.x == 0) {
        __threadfence();   // release: make h writes visible (fence.gpu; CCTL.IVALL)
        ull tok = atomicAdd(&g_bar2[bg][0], 1ULL) + 1ULL;
        ull target = ((tok + 7ULL) >> 3) << 3;
        for (;;) {
            ull v;
            asm volatile("ld.volatile.global.u64 %0, [%1];" : "=l"(v) : "l"(&g_bar2[bg][0]));
            if (v >= target) break;
        }
        __threadfence();   // acquire: invalidate L1D so peers' h is visible
    }
    __syncthreads();
}

// ------------------------------ copy --------------------------------------
__global__ void copy_kernel(float* __restrict__ dst, const float* __restrict__ src, int n) {
    int i = blockIdx.x * blockDim.x + threadIdx.x;
    if (i < n) dst[i] = src[i];
}

// ---------------------------------------------------------------------------
// Input projection GEMM: C[m][g] = bias[g] + sum_k A[m][k] * W[g][k]
// M = 131072, N = 768, K in {128, 256}. Tile 128x128x16, 256 threads,
// 8x8 per-thread microtile, col-paired f32x2 accumulators, register-prefetch
// pipeline on the K-chunks.
// ---------------------------------------------------------------------------
__global__ void __launch_bounds__(256, 2)
gemm_gx_kernel(const float* __restrict__ A, const float* __restrict__ W,
               const float* __restrict__ bias, float* __restrict__ C, int K)
{
    __shared__ float As[128][20];    // [m][k] (padded)
    __shared__ float Bs[16][132];    // [k][n] (padded, 16B-aligned rows)

    const int m0 = blockIdx.x * 128;
    const int n0 = blockIdx.y * 128;
    const int tid = threadIdx.x;
    const int ty = tid >> 4;         // 0..15 -> rows ty*8..+7
    const int tx = tid & 15;         // 0..15 -> cols tx*8..+7
    const int sr = tid >> 1;         // 0..127 staging row
    const int sk = (tid & 1) * 8;    // staging k-offset

    const float* Ag = A + (size_t)(m0 + sr) * K + sk;
    const float* Bg = W + (size_t)(n0 + sr) * K + sk;

    ull acc[8][4];
    #pragma unroll
    for (int i = 0; i < 8; ++i)
        #pragma unroll
        for (int j = 0; j < 4; ++j) acc[i][j] = 0ULL;

    float ar[8], br[8];
    {
        float4 a0 = *(const float4*)(Ag);
        float4 a1 = *(const float4*)(Ag + 4);
        float4 b0 = *(const float4*)(Bg);
        float4 b1 = *(const float4*)(Bg + 4);
        ar[0]=a0.x; ar[1]=a0.y; ar[2]=a0.z; ar[3]=a0.w;
        ar[4]=a1.x; ar[5]=a1.y; ar[6]=a1.z; ar[7]=a1.w;
        br[0]=b0.x; br[1]=b0.y; br[2]=b0.z; br[3]=b0.w;
        br[4]=b1.x; br[5]=b1.y; br[6]=b1.z; br[7]=b1.w;
    }

    const int nch = K >> 4;
    for (int c = 0; c < nch; ++c) {
        __syncthreads();
        #pragma unroll
        for (int j = 0; j < 8; ++j) { As[sr][sk + j] = ar[j]; Bs[sk + j][sr] = br[j]; }
        __syncthreads();

        if (c + 1 < nch) {
            const float* Ap = Ag + (c + 1) * 16;
            const float* Bp = Bg + (c + 1) * 16;
            float4 a0 = *(const float4*)(Ap);
            float4 a1 = *(const float4*)(Ap + 4);
            float4 b0 = *(const float4*)(Bp);
            float4 b1 = *(const float4*)(Bp + 4);
            ar[0]=a0.x; ar[1]=a0.y; ar[2]=a0.z; ar[3]=a0.w;
            ar[4]=a1.x; ar[5]=a1.y; ar[6]=a1.z; ar[7]=a1.w;
            br[0]=b0.x; br[1]=b0.y; br[2]=b0.z; br[3]=b0.w;
            br[4]=b1.x; br[5]=b1.y; br[6]=b1.z; br[7]=b1.w;
        }

        #pragma unroll 8
        for (int kk = 0; kk < 16; ++kk) {
            float av[8];
            #pragma unroll
            for (int i = 0; i < 8; ++i) av[i] = As[ty * 8 + i][kk];
            ulonglong2 bp0 = *(const ulonglong2*)(&Bs[kk][tx * 8]);
            ulonglong2 bp1 = *(const ulonglong2*)(&Bs[kk][tx * 8 + 4]);
            ull bq0 = bp0.x, bq1 = bp0.y, bq2 = bp1.x, bq3 = bp1.y;
            #pragma unroll
            for (int i = 0; i < 8; ++i) {
                ull a2 = pack2(av[i], av[i]);
                fma2(acc[i][0], a2, bq0);
                fma2(acc[i][1], a2, bq1);
                fma2(acc[i][2], a2, bq2);
                fma2(acc[i][3], a2, bq3);
            }
        }
    }

    float4 blo = *(const float4*)(bias + n0 + tx * 8);
    float4 bhi = *(const float4*)(bias + n0 + tx * 8 + 4);
    #pragma unroll
    for (int i = 0; i < 8; ++i) {
        float2 c0 = unpack2(acc[i][0]);
        float2 c1 = unpack2(acc[i][1]);
        float2 c2 = unpack2(acc[i][2]);
        float2 c3 = unpack2(acc[i][3]);
        float4 o0 = { c0.x + blo.x, c0.y + blo.y, c1.x + blo.z, c1.y + blo.w };
        float4 o1 = { c2.x + bhi.x, c2.y + bhi.y, c3.x + bhi.z, c3.y + bhi.w };
        float* cp = C + (size_t)(m0 + ty * 8 + i) * G_SZ + n0 + tx * 8;
        *(float4*)cp = o0;
        *(float4*)(cp + 4) = o1;
    }
}

// ---------------------------------------------------------------------------
// Persistent recurrent scan for one layer.
// Grid = 128 CTAs (16 b-groups x 8 h-groups), 128 threads/CTA.
// Lane map: warp covers 16 rows x 2 col-groups -> W smem reads are 96B/warp/k
// (broadcast), crossbar no longer binds. h[t-1] read directly from `out`.
// Barriers only span the 8 CTAs of one b-group.
// ---------------------------------------------------------------------------
#define SCAN_SMEM (96 * 256 * 4 + 16 * 260 * 4)   // 114944 bytes

__global__ void __launch_bounds__(128)
gru_scan_kernel(const float* __restrict__ Whh,   // [768][256]
                const float* __restrict__ bhh,   // [768]
                const float* __restrict__ gx,    // [T*B][768]
                const float* __restrict__ hinit, // [B][256]  (h0 for this layer)
                float* __restrict__ out)         // [T*B][256]
{
    extern __shared__ float smem[];
    float* Ws = smem;               // [256][96]  (k-major)
    float* hs = smem + 96 * 256;    // [16][260]  (row padded)

    const int tid = threadIdx.x;
    const int bg = blockIdx.x >> 3;   // 0..15
    const int hg = blockIdx.x & 7;    // 0..7
    const int b0 = bg * 16;
    const int h0 = hg * 32;

    // Load + transpose W slice once: Ws[k*96 + j] = Whh[(gt*256 + h0 + col)][k]
    for (int idx = tid; idx < 96 * 256; idx += 128) {
        int j = idx >> 8;          // 0..95
        int k = idx & 255;
        int gt = j >> 5, col = j & 31;
        Ws[k * 96 + j] = Whh[(size_t)(gt * 256 + h0 + col) * 256 + k];
    }

    const int w = tid >> 5;
    const int l = tid & 31;
    const int r  = l & 15;             // row 0..15 within tile
    const int cg = w * 2 + (l >> 4);   // col-group 0..7
    const int cb = h0 + cg * 4;        // global h-column base
    const int b  = b0 + r;

    float4 brv = *(const float4*)(bhh + cb);
    float4 bzv = *(const float4*)(bhh + 256 + cb);
    float4 bnv = *(const float4*)(bhh + 512 + cb);

    __syncthreads();

    for (int t = 0; t < T_LEN; ++t) {
        // gx prefetch (independent of h) — issue before staging/barrier work
        const float* gxr = gx + ((size_t)t * B_SZ + b) * G_SZ;
        float4 ir  = *(const float4*)(gxr + cb);
        float4 iz  = *(const float4*)(gxr + 256 + cb);
        float4 inn = *(const float4*)(gxr + 512 + cb);

        // stage h tile [16 x 256] -> hs (padded rows of 260)
        const float* hsrc = (t == 0) ? (hinit + (size_t)b0 * 256)
                                     : (out + ((size_t)(t - 1) * B_SZ + b0) * 256);
        for (int f = tid; f < 1024; f += 128) {
            int row = f >> 6;
            int kf = (f & 63) << 2;
            *(float4*)(hs + row * 260 + kf) = *(const float4*)(hsrc + row * 256 + kf);
        }
        __syncthreads();

        ull aR0 = 0, aR1 = 0, aZ0 = 0, aZ1 = 0, aN0 = 0, aN1 = 0;
        const float* hr = hs + r * 260;
        const float* wp = Ws + cg * 4;

        #pragma unroll 2
        for (int k0 = 0; k0 < 256; k0 += 4) {
            float4 h4 = *(const float4*)(hr + k0);
            #pragma unroll
            for (int u = 0; u < 4; ++u) {
                float a = (u == 0) ? h4.x : (u == 1) ? h4.y : (u == 2) ? h4.z : h4.w;
                ull a2 = pack2(a, a);
                const float* wk = wp + (k0 + u) * 96;
                ulonglong2 wr = *(const ulonglong2*)(wk);
                ulonglong2 wz = *(const ulonglong2*)(wk + 32);
                ulonglong2 wn = *(const ulonglong2*)(wk + 64);
                fma2(aR0, a2, wr.x); fma2(aR1, a2, wr.y);
                fma2(aZ0, a2, wz.x); fma2(aZ1, a2, wz.y);
                fma2(aN0, a2, wn.x); fma2(aN1, a2, wn.y);
            }
        }

        float4 hp = *(const float4*)(hr + cb);

        float2 r01 = unpack2(aR0), r23 = unpack2(aR1);
        float2 z01 = unpack2(aZ0), z23 = unpack2(aZ1);
        float2 n01 = unpack2(aN0), n23 = unpack2(aN1);

        float rg0 = sigmf(ir.x + r01.x + brv.x);
        float rg1 = sigmf(ir.y + r01.y + brv.y);
        float rg2 = sigmf(ir.z + r23.x + brv.z);
        float rg3 = sigmf(ir.w + r23.y + brv.w);

        float zg0 = sigmf(iz.x + z01.x + bzv.x);
        float zg1 = sigmf(iz.y + z01.y + bzv.y);
        float zg2 = sigmf(iz.z + z23.x + bzv.z);
        float zg3 = sigmf(iz.w + z23.y + bzv.w);

        float ng0 = tanhf(inn.x + rg0 * (n01.x + bnv.x));
        float ng1 = tanhf(inn.y + rg1 * (n01.y + bnv.y));
        float ng2 = tanhf(inn.z + rg2 * (n23.x + bnv.z));
        float ng3 = tanhf(inn.w + rg3 * (n23.y + bnv.w));

        float4 hv;
        hv.x = (1.0f - zg0) * ng0 + zg0 * hp.x;
        hv.y = (1.0f - zg1) * ng1 + zg1 * hp.y;
        hv.z = (1.0f - zg2) * ng2 + zg2 * hp.z;
        hv.w = (1.0f - zg3) * ng3 + zg3 * hp.w;

        *(float4*)(out + ((size_t)t * B_SZ + b) * 256 + cb) = hv;

        if (t != T_LEN - 1) bg_barrier(bg);
        __syncthreads();   // protect hs reuse (stagers vs readers) across steps
    }
}

// ---------------------------------------------------------------------------
extern "C" void kernel_launch(void* const* d_in, const int* in_sizes, int n_in,
                              void* d_out, int out_size)
{
    const float* x     = (const float*)d_in[0];  // [512,256,128]
    const float* h0    = (const float*)d_in[1];  // [6,256,256]
    const float* Wih0  = (const float*)d_in[2];  // [768,128]
    const float* Wih   = (const float*)d_in[3];  // [5,768,256]
    const float* Whh   = (const float*)d_in[4];  // [6,768,256]
    const float* bih   = (const float*)d_in[5];  // [6,768]
    const float* bhh   = (const float*)d_in[6];  // [6,768]
    float* out = (float*)d_out;

    float *gx_p = nullptr, *buf_p = nullptr;
    cudaGetSymbolAddress((void**)&gx_p,  g_gx);
    cudaGetSymbolAddress((void**)&buf_p, g_buf);

    cudaFuncSetAttribute(gru_scan_kernel,
                         cudaFuncAttributeMaxDynamicSharedMemorySize, SCAN_SMEM);

    for (int l = 0; l < L_NUM; ++l) {
        const float* in  = (l == 0) ? x   : buf_p + (size_t)((l - 1) & 1) * TBH;
        float*       lo  = (l == L_NUM - 1) ? out : buf_p + (size_t)(l & 1) * TBH;
        const int    K   = (l == 0) ? I_SZ : H_SZ;
        const float* Wi  = (l == 0) ? Wih0 : Wih + (size_t)(l - 1) * G_SZ * H_SZ;
        const float* Wh  = Whh + (size_t)l * G_SZ * H_SZ;
        const float* bi  = bih + (size_t)l * G_SZ;
        const float* bh  = bhh + (size_t)l * G_SZ;

        // gx = in @ Wi^T + bi   for all timesteps (one big parallel GEMM)
        dim3 gg(M_ROWS / 128, G_SZ / 128);
        gemm_gx_kernel<<<gg, 256>>>(in, Wi, bi, gx_p, K);

        // recurrent scan (persistent, 128 co-resident CTAs, per-bg barriers)
        gru_scan_kernel<<<128, 128, SCAN_SMEM>>>(Wh, bh, gx_p,
                                                 h0 + (size_t)l * BH, lo);

        // finals[l] = h after 512 steps = out rows of t=511
        copy_kernel<<<BH / 256, 256>>>(out + TBH + (size_t)l * BH,
                                       lo + (size_t)511 * BH, BH);
    }
}